// round 10
// baseline (speedup 1.0000x reference)
#include <cuda_runtime.h>
#include <cstdint>

// Sinkhorn on B x 64 x 64 matrices, scaling-vector form, one warp per matrix,
// one 32-thread CTA per matrix. K frozen in registers. Reduce-scatter -> rcp,
// with row scales gathered on-the-fly at each use (no rv2 array) and the
// prologue row-max kept scalar, trimming peak regs so 13 CTAs/SM fit.

typedef unsigned long long u64;
#define FULLMASK 0xffffffffu

__device__ __forceinline__ u64 pk2(float lo, float hi){
    u64 r; asm("mov.b64 %0, {%1, %2};" : "=l"(r) : "f"(lo), "f"(hi)); return r;
}
__device__ __forceinline__ void up2(u64 p, float& lo, float& hi){
    asm("mov.b64 {%0, %1}, %2;" : "=f"(lo), "=f"(hi) : "l"(p));
}
__device__ __forceinline__ u64 addx2(u64 a, u64 b){
    u64 r; asm("add.rn.f32x2 %0, %1, %2;" : "=l"(r) : "l"(a), "l"(b)); return r;
}
__device__ __forceinline__ u64 mulx2(u64 a, u64 b){
    u64 r; asm("mul.rn.f32x2 %0, %1, %2;" : "=l"(r) : "l"(a), "l"(b)); return r;
}
__device__ __forceinline__ u64 fmax2(u64 a, u64 b, u64 c){
    u64 r; asm("fma.rn.f32x2 %0, %1, %2, %3;" : "=l"(r) : "l"(a), "l"(b), "l"(c)); return r;
}
__device__ __forceinline__ float frcp(float x){
    float r; asm("rcp.approx.f32 %0, %1;" : "=f"(r) : "f"(x)); return r;
}
__device__ __forceinline__ float fex2(float x){
    float r; asm("ex2.approx.f32 %0, %1;" : "=f"(r) : "f"(x)); return r;
}
__device__ __forceinline__ u64 shfl64(u64 v, int m){
    return __shfl_xor_sync(FULLMASK, v, m);
}
__device__ __forceinline__ u64 shfl64i(u64 v, int src){
    return __shfl_sync(FULLMASK, v, src, 32);
}

// Precomputed softplus(-gamma) * (1/temp) * log2(e), shared by all batches.
__device__ float d_gp2[64 * 64];

__global__ void prep_kernel(const float* __restrict__ gamma){
    int i = blockIdx.x * blockDim.x + threadIdx.x;
    if (i < 64 * 64){
        float g = gamma[i];
        float sp = (g > 0.f) ? log1pf(expf(-g)) : (-g + log1pf(expf(g)));
        d_gp2[i] = sp * 14.4269504088896341f;   // * 10 (1/temp) * log2(e)
    }
}

__global__ void __launch_bounds__(32, 13) sinkhorn_kernel(
        const float* __restrict__ noise, float* __restrict__ out){
    int gw = blockIdx.x;                        // matrix id (grid = B)
    int lane = threadIdx.x;
    int tj = lane & 7;        // column group (8 groups of 8 cols)
    int ti = lane >> 3;       // row group    (4 groups of 16 rows)
    int row0 = ti * 16, col0 = tj * 8;
    int gbase = lane & 24;    // base lane of this tj-group

    const float* np = noise + ((size_t)gw * 64 + row0) * 64 + col0;
    const float* gp = d_gp2 + row0 * 64 + col0;
    const float KS = 14.4269504088896341f;     // 10 * log2(e)

    // Frozen kernel tile: 16 rows x 8 cols per lane; K[r][p] = cols (2p,2p+1).
    u64 K[16][4];

    // ---- load, scale into log2 domain, per-row max + exp, fused per row ----
    #pragma unroll
    for (int r = 0; r < 16; ++r){
        float4 n0 = *(const float4*)(np + (size_t)r * 64);
        float4 n1 = *(const float4*)(np + (size_t)r * 64 + 4);
        float4 g0 = *(const float4*)(gp + r * 64);
        float4 g1 = *(const float4*)(gp + r * 64 + 4);
        float x0 = fmaf(n0.x, KS, g0.x);
        float x1 = fmaf(n0.y, KS, g0.y);
        float x2 = fmaf(n0.z, KS, g0.z);
        float x3 = fmaf(n0.w, KS, g0.w);
        float x4 = fmaf(n1.x, KS, g1.x);
        float x5 = fmaf(n1.y, KS, g1.y);
        float x6 = fmaf(n1.z, KS, g1.z);
        float x7 = fmaf(n1.w, KS, g1.w);
        float mm = fmaxf(fmaxf(fmaxf(x0, x1), fmaxf(x2, x3)),
                         fmaxf(fmaxf(x4, x5), fmaxf(x6, x7)));
        mm = fmaxf(mm, __shfl_xor_sync(FULLMASK, mm, 1));
        mm = fmaxf(mm, __shfl_xor_sync(FULLMASK, mm, 2));
        mm = fmaxf(mm, __shfl_xor_sync(FULLMASK, mm, 4));
        K[r][0] = pk2(fex2(x0 - mm), fex2(x1 - mm));
        K[r][1] = pk2(fex2(x2 - mm), fex2(x3 - mm));
        K[r][2] = pk2(fex2(x4 - mm), fex2(x5 - mm));
        K[r][3] = pk2(fex2(x6 - mm), fex2(x7 - mm));
    }

    // Iteration state: c2[q] = (c_{col0+2q}, c_{col0+2q+1}); own_rv = packed
    // reciprocal row sums for this lane's owned row pair (pair index tj).
    u64 c2[4];
    c2[0] = pk2(1.f, 1.f); c2[1] = c2[0]; c2[2] = c2[0]; c2[3] = c2[0];
    u64 own_rv = pk2(1.f, 1.f);

    bool h4 = (tj & 4) != 0, h2 = (tj & 2) != 0, h1 = (tj & 1) != 0;
    bool g8 = (ti & 1) != 0, g16 = (ti & 2) != 0;

    #pragma unroll 1
    for (int it = 0; it < 50; ++it){
        // ---- row partial sums: pr[k] packs rows (2k, 2k+1) ----
        u64 pr[8];
        #pragma unroll
        for (int k = 0; k < 8; ++k){
            int r0 = 2 * k, r1 = r0 + 1;
            u64 a0 = mulx2(K[r0][0], c2[0]);
            u64 b0 = mulx2(K[r0][1], c2[1]);
            a0 = fmax2(K[r0][2], c2[2], a0);
            b0 = fmax2(K[r0][3], c2[3], b0);
            u64 a1 = mulx2(K[r1][0], c2[0]);
            u64 b1 = mulx2(K[r1][1], c2[1]);
            a1 = fmax2(K[r1][2], c2[2], a1);
            b1 = fmax2(K[r1][3], c2[3], b1);
            a0 = addx2(a0, b0);
            a1 = addx2(a1, b1);
            float a, b, d, e;
            up2(a0, a, b); up2(a1, d, e);
            pr[k] = pk2(a + b, d + e);
        }
        // ---- reduce-scatter over tj: lane ends owning pair index tj ----
        u64 n4[4];
        #pragma unroll
        for (int k = 0; k < 4; ++k){
            u64 snd = h4 ? pr[k] : pr[k + 4];
            u64 rcv = shfl64(snd, 4);
            n4[k] = addx2(h4 ? pr[k + 4] : pr[k], rcv);
        }
        u64 n2[2];
        #pragma unroll
        for (int k = 0; k < 2; ++k){
            u64 snd = h2 ? n4[k] : n4[k + 2];
            u64 rcv = shfl64(snd, 2);
            n2[k] = addx2(h2 ? n4[k + 2] : n4[k], rcv);
        }
        u64 s;
        {
            u64 snd = h1 ? n2[0] : n2[1];
            u64 rcv = shfl64(snd, 1);
            s = addx2(h1 ? n2[1] : n2[0], rcv);
        }
        { float u, v; up2(s, u, v); own_rv = pk2(frcp(u), frcp(v)); }

        // ---- col partial sums over this lane's 16 rows (dual accumulators),
        //      row scales gathered on the fly (owner of pair j: lane gbase+j) ----
        u64 cpA[4], cpB[4];
        {
            u64 rv0 = shfl64i(own_rv, gbase);
            float lo, hi; up2(rv0, lo, hi);
            u64 bl = pk2(lo, lo), bh = pk2(hi, hi);
            #pragma unroll
            for (int p = 0; p < 4; ++p)
                cpA[p] = fmax2(K[1][p], bh, mulx2(K[0][p], bl));
        }
        {
            u64 rv4 = shfl64i(own_rv, gbase + 4);
            float lo, hi; up2(rv4, lo, hi);
            u64 bl = pk2(lo, lo), bh = pk2(hi, hi);
            #pragma unroll
            for (int p = 0; p < 4; ++p)
                cpB[p] = fmax2(K[9][p], bh, mulx2(K[8][p], bl));
        }
        #pragma unroll
        for (int j = 1; j < 4; ++j){
            u64 rvj = shfl64i(own_rv, gbase + j);
            float lo, hi; up2(rvj, lo, hi);
            u64 bl = pk2(lo, lo), bh = pk2(hi, hi);
            u64 rvk = shfl64i(own_rv, gbase + j + 4);
            float lo2, hi2; up2(rvk, lo2, hi2);
            u64 bl2 = pk2(lo2, lo2), bh2 = pk2(hi2, hi2);
            #pragma unroll
            for (int p = 0; p < 4; ++p){
                cpA[p] = fmax2(K[2 * j][p],     bl,  cpA[p]);
                cpA[p] = fmax2(K[2 * j + 1][p], bh,  cpA[p]);
                cpB[p] = fmax2(K[2 * j + 8][p], bl2, cpB[p]);
                cpB[p] = fmax2(K[2 * j + 9][p], bh2, cpB[p]);
            }
        }
        u64 cp[4];
        #pragma unroll
        for (int p = 0; p < 4; ++p) cp[p] = addx2(cpA[p], cpB[p]);

        // ---- reduce-scatter over ti: lane owns col pair q=2*(ti&1)+(ti>>1) ----
        u64 m2[2];
        #pragma unroll
        for (int k = 0; k < 2; ++k){
            u64 snd = g8 ? cp[k] : cp[k + 2];
            u64 rcv = shfl64(snd, 8);
            m2[k] = addx2(g8 ? cp[k + 2] : cp[k], rcv);
        }
        u64 sc;
        {
            u64 snd = g16 ? m2[0] : m2[1];
            u64 rcv = shfl64(snd, 16);
            sc = addx2(g16 ? m2[1] : m2[0], rcv);
        }
        float u, v; up2(sc, u, v);
        u64 own_c = pk2(frcp(u), frcp(v));
        // ---- allgather c pairs: owner of pair q is ti = (q>>1) + 2*(q&1) ----
        c2[0] = shfl64i(own_c, tj);
        c2[1] = shfl64i(own_c, tj + 16);
        c2[2] = shfl64i(own_c, tj + 8);
        c2[3] = shfl64i(own_c, tj + 24);
    }

    // ---- materialize out = diag(r) K diag(c) and store (regather rv) ----
    float* op = out + ((size_t)gw * 64 + row0) * 64 + col0;
    #pragma unroll
    for (int j = 0; j < 8; ++j){
        u64 rvj = shfl64i(own_rv, gbase + j);
        float lo, hi; up2(rvj, lo, hi);
        u64 bl = pk2(lo, lo), bh = pk2(hi, hi);
        int r0 = 2 * j, r1 = r0 + 1;
        u64 t0 = mulx2(mulx2(K[r0][0], bl), c2[0]);
        u64 t1 = mulx2(mulx2(K[r0][1], bl), c2[1]);
        u64 t2 = mulx2(mulx2(K[r0][2], bl), c2[2]);
        u64 t3 = mulx2(mulx2(K[r0][3], bl), c2[3]);
        u64 t4 = mulx2(mulx2(K[r1][0], bh), c2[0]);
        u64 t5 = mulx2(mulx2(K[r1][1], bh), c2[1]);
        u64 t6 = mulx2(mulx2(K[r1][2], bh), c2[2]);
        u64 t7 = mulx2(mulx2(K[r1][3], bh), c2[3]);
        float x0, x1, x2, x3, x4, x5, x6, x7;
        up2(t0, x0, x1); up2(t1, x2, x3); up2(t2, x4, x5); up2(t3, x6, x7);
        float* ra = op + (size_t)r0 * 64;
        *(float4*)(ra)     = make_float4(x0, x1, x2, x3);
        *(float4*)(ra + 4) = make_float4(x4, x5, x6, x7);
        up2(t4, x0, x1); up2(t5, x2, x3); up2(t6, x4, x5); up2(t7, x6, x7);
        float* rb = op + (size_t)r1 * 64;
        *(float4*)(rb)     = make_float4(x0, x1, x2, x3);
        *(float4*)(rb + 4) = make_float4(x4, x5, x6, x7);
    }
}

extern "C" void kernel_launch(void* const* d_in, const int* in_sizes, int n_in,
                              void* d_out, int out_size) {
    const float* gamma = (const float*)d_in[0];   // [64,64] fp32
    const float* noise = (const float*)d_in[1];   // [B,64,64] fp32
    float* out = (float*)d_out;                   // [B,64,64] fp32
    int B = in_sizes[1] / (64 * 64);

    prep_kernel<<<16, 256>>>(gamma);
    sinkhorn_kernel<<<B, 32>>>(noise, out);       // one 32-thread CTA per matrix
}

// round 11
// speedup vs baseline: 1.2173x; 1.2173x over previous
#include <cuda_runtime.h>
#include <cstdint>

// Sinkhorn on B x 64 x 64 matrices, scaling-vector form, one warp per matrix,
// one 32-thread CTA per matrix. K frozen in registers (168 regs, 12 warps/SM —
// measured ceiling). Row pass: reduce-scatter -> rcp -> allgather. Col pass:
// butterfly ALLREDUCE + redundant local rcp (removes the col allgather from
// the serial chain).

typedef unsigned long long u64;
#define FULLMASK 0xffffffffu

__device__ __forceinline__ u64 pk2(float lo, float hi){
    u64 r; asm("mov.b64 %0, {%1, %2};" : "=l"(r) : "f"(lo), "f"(hi)); return r;
}
__device__ __forceinline__ void up2(u64 p, float& lo, float& hi){
    asm("mov.b64 {%0, %1}, %2;" : "=f"(lo), "=f"(hi) : "l"(p));
}
__device__ __forceinline__ u64 addx2(u64 a, u64 b){
    u64 r; asm("add.rn.f32x2 %0, %1, %2;" : "=l"(r) : "l"(a), "l"(b)); return r;
}
__device__ __forceinline__ u64 mulx2(u64 a, u64 b){
    u64 r; asm("mul.rn.f32x2 %0, %1, %2;" : "=l"(r) : "l"(a), "l"(b)); return r;
}
__device__ __forceinline__ u64 fmax2(u64 a, u64 b, u64 c){
    u64 r; asm("fma.rn.f32x2 %0, %1, %2, %3;" : "=l"(r) : "l"(a), "l"(b), "l"(c)); return r;
}
__device__ __forceinline__ float frcp(float x){
    float r; asm("rcp.approx.f32 %0, %1;" : "=f"(r) : "f"(x)); return r;
}
__device__ __forceinline__ float fex2(float x){
    float r; asm("ex2.approx.f32 %0, %1;" : "=f"(r) : "f"(x)); return r;
}
__device__ __forceinline__ u64 shfl64(u64 v, int m){
    return __shfl_xor_sync(FULLMASK, v, m);
}
__device__ __forceinline__ u64 shfl64i(u64 v, int src){
    return __shfl_sync(FULLMASK, v, src, 32);
}

// Precomputed softplus(-gamma) * (1/temp) * log2(e), shared by all batches.
__device__ float d_gp2[64 * 64];

__global__ void prep_kernel(const float* __restrict__ gamma){
    int i = blockIdx.x * blockDim.x + threadIdx.x;
    if (i < 64 * 64){
        float g = gamma[i];
        float sp = (g > 0.f) ? log1pf(expf(-g)) : (-g + log1pf(expf(g)));
        d_gp2[i] = sp * 14.4269504088896341f;   // * 10 (1/temp) * log2(e)
    }
}

__global__ void __launch_bounds__(32, 12) sinkhorn_kernel(
        const float* __restrict__ noise, float* __restrict__ out){
    int gw = blockIdx.x;                        // matrix id (grid = B)
    int lane = threadIdx.x;
    int tj = lane & 7;        // column group (8 groups of 8 cols)
    int ti = lane >> 3;       // row group    (4 groups of 16 rows)
    int row0 = ti * 16, col0 = tj * 8;
    int gbase = lane & 24;    // base lane of this tj-group

    const float* np = noise + ((size_t)gw * 64 + row0) * 64 + col0;
    const float* gp = d_gp2 + row0 * 64 + col0;
    const float KS = 14.4269504088896341f;     // 10 * log2(e)

    // Frozen kernel tile: 16 rows x 8 cols per lane; K[r][p] = cols (2p,2p+1).
    u64 K[16][4];
    float m[16];

    #pragma unroll
    for (int r = 0; r < 16; ++r){
        float4 n0 = *(const float4*)(np + (size_t)r * 64);
        float4 n1 = *(const float4*)(np + (size_t)r * 64 + 4);
        float4 g0 = *(const float4*)(gp + r * 64);
        float4 g1 = *(const float4*)(gp + r * 64 + 4);
        float x0 = fmaf(n0.x, KS, g0.x);
        float x1 = fmaf(n0.y, KS, g0.y);
        float x2 = fmaf(n0.z, KS, g0.z);
        float x3 = fmaf(n0.w, KS, g0.w);
        float x4 = fmaf(n1.x, KS, g1.x);
        float x5 = fmaf(n1.y, KS, g1.y);
        float x6 = fmaf(n1.z, KS, g1.z);
        float x7 = fmaf(n1.w, KS, g1.w);
        K[r][0] = pk2(x0, x1);
        K[r][1] = pk2(x2, x3);
        K[r][2] = pk2(x4, x5);
        K[r][3] = pk2(x6, x7);
        m[r] = fmaxf(fmaxf(fmaxf(x0, x1), fmaxf(x2, x3)),
                     fmaxf(fmaxf(x4, x5), fmaxf(x6, x7)));
    }
    #pragma unroll
    for (int r = 0; r < 16; ++r){
        float mm = m[r];
        mm = fmaxf(mm, __shfl_xor_sync(FULLMASK, mm, 1));
        mm = fmaxf(mm, __shfl_xor_sync(FULLMASK, mm, 2));
        mm = fmaxf(mm, __shfl_xor_sync(FULLMASK, mm, 4));
        u64 nm = pk2(-mm, -mm);
        #pragma unroll
        for (int p = 0; p < 4; ++p){
            u64 t = addx2(K[r][p], nm);
            float u, v; up2(t, u, v);
            K[r][p] = pk2(fex2(u), fex2(v));
        }
    }

    // Iteration state: c2[q] = (c_{col0+2q}, c_{col0+2q+1}); rv2[j] = packed
    // reciprocal row sums for rows (row0+2j, row0+2j+1).
    u64 c2[4];
    c2[0] = pk2(1.f, 1.f); c2[1] = c2[0]; c2[2] = c2[0]; c2[3] = c2[0];
    u64 rv2[8];

    bool h4 = (tj & 4) != 0, h2 = (tj & 2) != 0, h1 = (tj & 1) != 0;

    #pragma unroll 1
    for (int it = 0; it < 50; ++it){
        // ---- row partial sums: pr[k] packs rows (2k, 2k+1) ----
        u64 pr[8];
        #pragma unroll
        for (int k = 0; k < 8; ++k){
            int r0 = 2 * k, r1 = r0 + 1;
            u64 a0 = mulx2(K[r0][0], c2[0]);
            u64 b0 = mulx2(K[r0][1], c2[1]);
            a0 = fmax2(K[r0][2], c2[2], a0);
            b0 = fmax2(K[r0][3], c2[3], b0);
            u64 a1 = mulx2(K[r1][0], c2[0]);
            u64 b1 = mulx2(K[r1][1], c2[1]);
            a1 = fmax2(K[r1][2], c2[2], a1);
            b1 = fmax2(K[r1][3], c2[3], b1);
            a0 = addx2(a0, b0);
            a1 = addx2(a1, b1);
            float a, b, d, e;
            up2(a0, a, b); up2(a1, d, e);
            pr[k] = pk2(a + b, d + e);
        }
        // ---- reduce-scatter over tj: lane ends owning pair index tj ----
        u64 n4[4];
        #pragma unroll
        for (int k = 0; k < 4; ++k){
            u64 snd = h4 ? pr[k] : pr[k + 4];
            u64 rcv = shfl64(snd, 4);
            n4[k] = addx2(h4 ? pr[k + 4] : pr[k], rcv);
        }
        u64 n2[2];
        #pragma unroll
        for (int k = 0; k < 2; ++k){
            u64 snd = h2 ? n4[k] : n4[k + 2];
            u64 rcv = shfl64(snd, 2);
            n2[k] = addx2(h2 ? n4[k + 2] : n4[k], rcv);
        }
        u64 s;
        {
            u64 snd = h1 ? n2[0] : n2[1];
            u64 rcv = shfl64(snd, 1);
            s = addx2(h1 ? n2[1] : n2[0], rcv);
        }
        u64 own_rv;
        { float u, v; up2(s, u, v); own_rv = pk2(frcp(u), frcp(v)); }
        // ---- allgather rv pairs (owner of pair j is lane gbase+j) ----
        #pragma unroll
        for (int j = 0; j < 8; ++j) rv2[j] = shfl64i(own_rv, gbase + j);

        // ---- col partial sums over this lane's 16 rows (dual accumulators) ----
        u64 cpA[4], cpB[4];
        {
            float lo, hi; up2(rv2[0], lo, hi);
            u64 bl = pk2(lo, lo), bh = pk2(hi, hi);
            #pragma unroll
            for (int p = 0; p < 4; ++p)
                cpA[p] = fmax2(K[1][p], bh, mulx2(K[0][p], bl));
        }
        {
            float lo, hi; up2(rv2[4], lo, hi);
            u64 bl = pk2(lo, lo), bh = pk2(hi, hi);
            #pragma unroll
            for (int p = 0; p < 4; ++p)
                cpB[p] = fmax2(K[9][p], bh, mulx2(K[8][p], bl));
        }
        #pragma unroll
        for (int j = 1; j < 4; ++j){
            float lo, hi; up2(rv2[j], lo, hi);
            u64 bl = pk2(lo, lo), bh = pk2(hi, hi);
            float lo2, hi2; up2(rv2[j + 4], lo2, hi2);
            u64 bl2 = pk2(lo2, lo2), bh2 = pk2(hi2, hi2);
            #pragma unroll
            for (int p = 0; p < 4; ++p){
                cpA[p] = fmax2(K[2 * j][p],     bl,  cpA[p]);
                cpA[p] = fmax2(K[2 * j + 1][p], bh,  cpA[p]);
                cpB[p] = fmax2(K[2 * j + 8][p], bl2, cpB[p]);
                cpB[p] = fmax2(K[2 * j + 9][p], bh2, cpB[p]);
            }
        }
        // ---- butterfly ALLREDUCE over ti (xor 8, 16) + local rcp ----
        // Every lane ends with the full column sums for its own 8 columns and
        // computes c2 directly; no ownership, no allgather on the serial path.
        #pragma unroll
        for (int p = 0; p < 4; ++p){
            u64 cp = addx2(cpA[p], cpB[p]);
            cp = addx2(cp, shfl64(cp, 8));
            cp = addx2(cp, shfl64(cp, 16));
            float u, v; up2(cp, u, v);
            c2[p] = pk2(frcp(u), frcp(v));
        }
    }

    // ---- materialize out = diag(r) K diag(c) and store ----
    float* op = out + ((size_t)gw * 64 + row0) * 64 + col0;
    #pragma unroll
    for (int j = 0; j < 8; ++j){
        float lo, hi; up2(rv2[j], lo, hi);
        u64 bl = pk2(lo, lo), bh = pk2(hi, hi);
        int r0 = 2 * j, r1 = r0 + 1;
        u64 t0 = mulx2(mulx2(K[r0][0], bl), c2[0]);
        u64 t1 = mulx2(mulx2(K[r0][1], bl), c2[1]);
        u64 t2 = mulx2(mulx2(K[r0][2], bl), c2[2]);
        u64 t3 = mulx2(mulx2(K[r0][3], bl), c2[3]);
        u64 t4 = mulx2(mulx2(K[r1][0], bh), c2[0]);
        u64 t5 = mulx2(mulx2(K[r1][1], bh), c2[1]);
        u64 t6 = mulx2(mulx2(K[r1][2], bh), c2[2]);
        u64 t7 = mulx2(mulx2(K[r1][3], bh), c2[3]);
        float x0, x1, x2, x3, x4, x5, x6, x7;
        up2(t0, x0, x1); up2(t1, x2, x3); up2(t2, x4, x5); up2(t3, x6, x7);
        float* ra = op + (size_t)r0 * 64;
        *(float4*)(ra)     = make_float4(x0, x1, x2, x3);
        *(float4*)(ra + 4) = make_float4(x4, x5, x6, x7);
        up2(t4, x0, x1); up2(t5, x2, x3); up2(t6, x4, x5); up2(t7, x6, x7);
        float* rb = op + (size_t)r1 * 64;
        *(float4*)(rb)     = make_float4(x0, x1, x2, x3);
        *(float4*)(rb + 4) = make_float4(x4, x5, x6, x7);
    }
}

extern "C" void kernel_launch(void* const* d_in, const int* in_sizes, int n_in,
                              void* d_out, int out_size) {
    const float* gamma = (const float*)d_in[0];   // [64,64] fp32
    const float* noise = (const float*)d_in[1];   // [B,64,64] fp32
    float* out = (float*)d_out;                   // [B,64,64] fp32
    int B = in_sizes[1] / (64 * 64);

    prep_kernel<<<16, 256>>>(gamma);
    sinkhorn_kernel<<<B, 32>>>(noise, out);       // one 32-thread CTA per matrix
}

// round 12
// speedup vs baseline: 1.4247x; 1.1704x over previous
#include <cuda_runtime.h>
#include <cstdint>

// Sinkhorn on B x 64 x 64 matrices, scaling-vector form, one warp per matrix,
// one 32-thread CTA per matrix (fluid scheduling). K frozen in registers
// (168 regs, 12 warps/SM = measured ceiling). Row pass: single-chain packed
// matvec (16 independent chains) -> reduce-scatter -> rcp -> allgather.
// Col pass: dual-accumulator matvec -> reduce-scatter -> rcp -> allgather.

typedef unsigned long long u64;
#define FULLMASK 0xffffffffu

__device__ __forceinline__ u64 pk2(float lo, float hi){
    u64 r; asm("mov.b64 %0, {%1, %2};" : "=l"(r) : "f"(lo), "f"(hi)); return r;
}
__device__ __forceinline__ void up2(u64 p, float& lo, float& hi){
    asm("mov.b64 {%0, %1}, %2;" : "=f"(lo), "=f"(hi) : "l"(p));
}
__device__ __forceinline__ u64 addx2(u64 a, u64 b){
    u64 r; asm("add.rn.f32x2 %0, %1, %2;" : "=l"(r) : "l"(a), "l"(b)); return r;
}
__device__ __forceinline__ u64 mulx2(u64 a, u64 b){
    u64 r; asm("mul.rn.f32x2 %0, %1, %2;" : "=l"(r) : "l"(a), "l"(b)); return r;
}
__device__ __forceinline__ u64 fmax2(u64 a, u64 b, u64 c){
    u64 r; asm("fma.rn.f32x2 %0, %1, %2, %3;" : "=l"(r) : "l"(a), "l"(b), "l"(c)); return r;
}
__device__ __forceinline__ float frcp(float x){
    float r; asm("rcp.approx.f32 %0, %1;" : "=f"(r) : "f"(x)); return r;
}
__device__ __forceinline__ float fex2(float x){
    float r; asm("ex2.approx.f32 %0, %1;" : "=f"(r) : "f"(x)); return r;
}
__device__ __forceinline__ u64 shfl64(u64 v, int m){
    return __shfl_xor_sync(FULLMASK, v, m);
}
__device__ __forceinline__ u64 shfl64i(u64 v, int src){
    return __shfl_sync(FULLMASK, v, src, 32);
}

// Precomputed softplus(-gamma) * (1/temp) * log2(e), shared by all batches.
__device__ float d_gp2[64 * 64];

__global__ void prep_kernel(const float* __restrict__ gamma){
    int i = blockIdx.x * blockDim.x + threadIdx.x;
    if (i < 64 * 64){
        float g = gamma[i];
        float sp = (g > 0.f) ? log1pf(expf(-g)) : (-g + log1pf(expf(g)));
        d_gp2[i] = sp * 14.4269504088896341f;   // * 10 (1/temp) * log2(e)
    }
}

__global__ void __launch_bounds__(32, 12) sinkhorn_kernel(
        const float* __restrict__ noise, float* __restrict__ out){
    int gw = blockIdx.x;                        // matrix id (grid = B)
    int lane = threadIdx.x;
    int tj = lane & 7;        // column group (8 groups of 8 cols)
    int ti = lane >> 3;       // row group    (4 groups of 16 rows)
    int row0 = ti * 16, col0 = tj * 8;
    int gbase = lane & 24;    // base lane of this tj-group

    const float* np = noise + ((size_t)gw * 64 + row0) * 64 + col0;
    const float* gp = d_gp2 + row0 * 64 + col0;
    const float KS = 14.4269504088896341f;     // 10 * log2(e)

    // Frozen kernel tile: 16 rows x 8 cols per lane; K[r][p] = cols (2p,2p+1).
    u64 K[16][4];
    float m[16];

    #pragma unroll
    for (int r = 0; r < 16; ++r){
        float4 n0 = *(const float4*)(np + (size_t)r * 64);
        float4 n1 = *(const float4*)(np + (size_t)r * 64 + 4);
        float4 g0 = *(const float4*)(gp + r * 64);
        float4 g1 = *(const float4*)(gp + r * 64 + 4);
        float x0 = fmaf(n0.x, KS, g0.x);
        float x1 = fmaf(n0.y, KS, g0.y);
        float x2 = fmaf(n0.z, KS, g0.z);
        float x3 = fmaf(n0.w, KS, g0.w);
        float x4 = fmaf(n1.x, KS, g1.x);
        float x5 = fmaf(n1.y, KS, g1.y);
        float x6 = fmaf(n1.z, KS, g1.z);
        float x7 = fmaf(n1.w, KS, g1.w);
        K[r][0] = pk2(x0, x1);
        K[r][1] = pk2(x2, x3);
        K[r][2] = pk2(x4, x5);
        K[r][3] = pk2(x6, x7);
        m[r] = fmaxf(fmaxf(fmaxf(x0, x1), fmaxf(x2, x3)),
                     fmaxf(fmaxf(x4, x5), fmaxf(x6, x7)));
    }
    #pragma unroll
    for (int r = 0; r < 16; ++r){
        float mm = m[r];
        mm = fmaxf(mm, __shfl_xor_sync(FULLMASK, mm, 1));
        mm = fmaxf(mm, __shfl_xor_sync(FULLMASK, mm, 2));
        mm = fmaxf(mm, __shfl_xor_sync(FULLMASK, mm, 4));
        u64 nm = pk2(-mm, -mm);
        #pragma unroll
        for (int p = 0; p < 4; ++p){
            u64 t = addx2(K[r][p], nm);
            float u, v; up2(t, u, v);
            K[r][p] = pk2(fex2(u), fex2(v));
        }
    }

    // Iteration state: c2[q] = (c_{col0+2q}, c_{col0+2q+1}); rv2[j] = packed
    // reciprocal row sums for rows (row0+2j, row0+2j+1).
    u64 c2[4];
    c2[0] = pk2(1.f, 1.f); c2[1] = c2[0]; c2[2] = c2[0]; c2[3] = c2[0];
    u64 rv2[8];

    bool h4 = (tj & 4) != 0, h2 = (tj & 2) != 0, h1 = (tj & 1) != 0;
    bool g8 = (ti & 1) != 0, g16 = (ti & 2) != 0;

    #pragma unroll 1
    for (int it = 0; it < 50; ++it){
        // ---- row partial sums: single-chain per row, 16 independent chains ----
        u64 pr[8];
        #pragma unroll
        for (int k = 0; k < 8; ++k){
            int r0 = 2 * k, r1 = r0 + 1;
            u64 a0 = mulx2(K[r0][0], c2[0]);
            a0 = fmax2(K[r0][1], c2[1], a0);
            a0 = fmax2(K[r0][2], c2[2], a0);
            a0 = fmax2(K[r0][3], c2[3], a0);
            u64 a1 = mulx2(K[r1][0], c2[0]);
            a1 = fmax2(K[r1][1], c2[1], a1);
            a1 = fmax2(K[r1][2], c2[2], a1);
            a1 = fmax2(K[r1][3], c2[3], a1);
            float a, b, d, e;
            up2(a0, a, b); up2(a1, d, e);
            pr[k] = pk2(a + b, d + e);
        }
        // ---- reduce-scatter over tj: lane ends owning pair index tj ----
        u64 n4[4];
        #pragma unroll
        for (int k = 0; k < 4; ++k){
            u64 snd = h4 ? pr[k] : pr[k + 4];
            u64 rcv = shfl64(snd, 4);
            n4[k] = addx2(h4 ? pr[k + 4] : pr[k], rcv);
        }
        u64 n2[2];
        #pragma unroll
        for (int k = 0; k < 2; ++k){
            u64 snd = h2 ? n4[k] : n4[k + 2];
            u64 rcv = shfl64(snd, 2);
            n2[k] = addx2(h2 ? n4[k + 2] : n4[k], rcv);
        }
        u64 s;
        {
            u64 snd = h1 ? n2[0] : n2[1];
            u64 rcv = shfl64(snd, 1);
            s = addx2(h1 ? n2[1] : n2[0], rcv);
        }
        u64 own_rv;
        { float u, v; up2(s, u, v); own_rv = pk2(frcp(u), frcp(v)); }
        // ---- allgather rv pairs (owner of pair j is lane gbase+j) ----
        #pragma unroll
        for (int j = 0; j < 8; ++j) rv2[j] = shfl64i(own_rv, gbase + j);

        // ---- col partial sums over this lane's 16 rows (dual accumulators) ----
        u64 cpA[4], cpB[4];
        {
            float lo, hi; up2(rv2[0], lo, hi);
            u64 bl = pk2(lo, lo), bh = pk2(hi, hi);
            #pragma unroll
            for (int p = 0; p < 4; ++p)
                cpA[p] = fmax2(K[1][p], bh, mulx2(K[0][p], bl));
        }
        {
            float lo, hi; up2(rv2[4], lo, hi);
            u64 bl = pk2(lo, lo), bh = pk2(hi, hi);
            #pragma unroll
            for (int p = 0; p < 4; ++p)
                cpB[p] = fmax2(K[9][p], bh, mulx2(K[8][p], bl));
        }
        #pragma unroll
        for (int j = 1; j < 4; ++j){
            float lo, hi; up2(rv2[j], lo, hi);
            u64 bl = pk2(lo, lo), bh = pk2(hi, hi);
            float lo2, hi2; up2(rv2[j + 4], lo2, hi2);
            u64 bl2 = pk2(lo2, lo2), bh2 = pk2(hi2, hi2);
            #pragma unroll
            for (int p = 0; p < 4; ++p){
                cpA[p] = fmax2(K[2 * j][p],     bl,  cpA[p]);
                cpA[p] = fmax2(K[2 * j + 1][p], bh,  cpA[p]);
                cpB[p] = fmax2(K[2 * j + 8][p], bl2, cpB[p]);
                cpB[p] = fmax2(K[2 * j + 9][p], bh2, cpB[p]);
            }
        }
        u64 cp[4];
        #pragma unroll
        for (int p = 0; p < 4; ++p) cp[p] = addx2(cpA[p], cpB[p]);

        // ---- reduce-scatter over ti: lane owns col pair q=2*(ti&1)+(ti>>1) ----
        u64 m2[2];
        #pragma unroll
        for (int k = 0; k < 2; ++k){
            u64 snd = g8 ? cp[k] : cp[k + 2];
            u64 rcv = shfl64(snd, 8);
            m2[k] = addx2(g8 ? cp[k + 2] : cp[k], rcv);
        }
        u64 sc;
        {
            u64 snd = g16 ? m2[0] : m2[1];
            u64 rcv = shfl64(snd, 16);
            sc = addx2(g16 ? m2[1] : m2[0], rcv);
        }
        float u, v; up2(sc, u, v);
        u64 own_c = pk2(frcp(u), frcp(v));
        // ---- allgather c pairs: owner of pair q is ti = (q>>1) + 2*(q&1) ----
        c2[0] = shfl64i(own_c, tj);
        c2[1] = shfl64i(own_c, tj + 16);
        c2[2] = shfl64i(own_c, tj + 8);
        c2[3] = shfl64i(own_c, tj + 24);
    }

    // ---- materialize out = diag(r) K diag(c) and store ----
    float* op = out + ((size_t)gw * 64 + row0) * 64 + col0;
    #pragma unroll
    for (int j = 0; j < 8; ++j){
        float lo, hi; up2(rv2[j], lo, hi);
        u64 bl = pk2(lo, lo), bh = pk2(hi, hi);
        int r0 = 2 * j, r1 = r0 + 1;
        u64 t0 = mulx2(mulx2(K[r0][0], bl), c2[0]);
        u64 t1 = mulx2(mulx2(K[r0][1], bl), c2[1]);
        u64 t2 = mulx2(mulx2(K[r0][2], bl), c2[2]);
        u64 t3 = mulx2(mulx2(K[r0][3], bl), c2[3]);
        u64 t4 = mulx2(mulx2(K[r1][0], bh), c2[0]);
        u64 t5 = mulx2(mulx2(K[r1][1], bh), c2[1]);
        u64 t6 = mulx2(mulx2(K[r1][2], bh), c2[2]);
        u64 t7 = mulx2(mulx2(K[r1][3], bh), c2[3]);
        float x0, x1, x2, x3, x4, x5, x6, x7;
        up2(t0, x0, x1); up2(t1, x2, x3); up2(t2, x4, x5); up2(t3, x6, x7);
        float* ra = op + (size_t)r0 * 64;
        *(float4*)(ra)     = make_float4(x0, x1, x2, x3);
        *(float4*)(ra + 4) = make_float4(x4, x5, x6, x7);
        up2(t4, x0, x1); up2(t5, x2, x3); up2(t6, x4, x5); up2(t7, x6, x7);
        float* rb = op + (size_t)r1 * 64;
        *(float4*)(rb)     = make_float4(x0, x1, x2, x3);
        *(float4*)(rb + 4) = make_float4(x4, x5, x6, x7);
    }
}

extern "C" void kernel_launch(void* const* d_in, const int* in_sizes, int n_in,
                              void* d_out, int out_size) {
    const float* gamma = (const float*)d_in[0];   // [64,64] fp32
    const float* noise = (const float*)d_in[1];   // [B,64,64] fp32
    float* out = (float*)d_out;                   // [B,64,64] fp32
    int B = in_sizes[1] / (64 * 64);

    prep_kernel<<<16, 256>>>(gamma);
    sinkhorn_kernel<<<B, 32>>>(noise, out);       // one 32-thread CTA per matrix
}